// round 5
// baseline (speedup 1.0000x reference)
#include <cuda_runtime.h>
#include <cstdint>

// ConditionalSplineSQ2D: out[b] = sum_{g,h,c} param[b,g,h,ii]*param[b,g,h,jj]*coef[g,h,c]
// B=4096, G*G=961 cells, P=8, C=36. Pure HBM stream: 126MB read once.
//
// Coefs live in SMEM transposed (cfs[c*961+cell], conflict-free LDS across
// lanes) instead of 36 registers/thread -- that regfile pressure (55% of the
// RF) was capping per-warp MLP. Freed registers fund: 2 b's per iteration
// with packed fma.rn.f32x2 (each coef LDS feeds both b's), and a pair-deep
// register prefetch (64B/thread in flight = 64KB/SM). Block reduction is
// batched: one __syncthreads per 4 pairs (8 b's), warp w finalizes b_w.

#define GG     961
#define CC     36
#define NTHR   1024
#define PAIRS  4          // pairs per reduction batch (8 b's)

extern __shared__ float cfs[];     // [CC*GG] transposed coefs

__device__ __forceinline__ unsigned long long pk2(float lo, float hi) {
    unsigned long long r;
    asm("mov.b64 %0, {%1, %2};" : "=l"(r) : "f"(lo), "f"(hi));
    return r;
}
__device__ __forceinline__ unsigned long long pk1(float v) {
    unsigned long long r;
    asm("mov.b64 %0, {%1, %1};" : "=l"(r) : "f"(v));
    return r;
}
__device__ __forceinline__ void fma2(unsigned long long& d,
                                     unsigned long long a,
                                     unsigned long long b) {
    asm("fma.rn.f32x2 %0, %1, %2, %0;" : "+l"(d) : "l"(a), "l"(b));
}
__device__ __forceinline__ void unpk2(float& lo, float& hi, unsigned long long v) {
    asm("mov.b64 {%0, %1}, %2;" : "=f"(lo), "=f"(hi) : "l"(v));
}

__global__ __launch_bounds__(NTHR, 1)
void sq2d_kernel(const float* __restrict__ param,
                 const float* __restrict__ coef,
                 float* __restrict__ out,
                 int nB, int stride)
{
    __shared__ float red[2][PAIRS][2][32];

    const int tid  = threadIdx.x;
    const int lane = tid & 31;
    const int warp = tid >> 5;
    const bool active = (tid < GG);
    const int cell = active ? tid : (GG - 1);

    // Cooperative transposed fill: cfs[c*GG + cell] = coef[cell*CC + c].
    // Reads coalesced over idx; writes stride GG(odd) words -> conflict-free.
    for (int idx = tid; idx < GG * CC; idx += NTHR) {
        int cel = idx / CC;
        int c   = idx - cel * CC;
        cfs[c * GG + cel] = coef[idx];
    }
    __syncthreads();

    const float4* pbase = reinterpret_cast<const float4*>(param) + (size_t)cell * 2;
    const size_t bstep4 = (size_t)GG * 2;
    const int pstride = 2 * stride;

    // Prefetch first pair (b, b+stride).
    float4 c00 = {0,0,0,0}, c01 = {0,0,0,0}, c10 = {0,0,0,0}, c11 = {0,0,0,0};
    int b = blockIdx.x;
    if (b < nB)          { const float4* p = pbase + (size_t)b * bstep4;            c00 = p[0]; c01 = p[1]; }
    if (b + stride < nB) { const float4* p = pbase + (size_t)(b + stride) * bstep4; c10 = p[0]; c11 = p[1]; }

    int buf = 0;
    while (b < nB) {
        const int bstart = b;
        int npairs = 0;

#pragma unroll 1
        for (int k2 = 0; k2 < PAIRS && b < nB; k2++) {
            float4 a00 = c00, a01 = c01, a10 = c10, a11 = c11;

            // Prefetch next pair immediately (lands over this pair's compute
            // plus the batch-mates' work).
            const int bn = b + pstride;
            if (bn < nB)          { const float4* p = pbase + (size_t)bn * bstep4;            c00 = p[0]; c01 = p[1]; }
            if (bn + stride < nB) { const float4* p = pbase + (size_t)(bn + stride) * bstep4; c10 = p[0]; c11 = p[1]; }

            // Pack {b0, b1} lanes into f32x2 registers.
            unsigned long long pv2[8];
            pv2[0] = pk2(a00.x, a10.x);  pv2[1] = pk2(a00.y, a10.y);
            pv2[2] = pk2(a00.z, a10.z);  pv2[3] = pk2(a00.w, a10.w);
            pv2[4] = pk2(a01.x, a11.x);  pv2[5] = pk2(a01.y, a11.y);
            pv2[6] = pk2(a01.z, a11.z);  pv2[7] = pk2(a01.w, a11.w);

            // acc = sum_{i<=j} cf * p_i * p_j for both b's at once: 44 FFMA2.
            unsigned long long acc2 = 0ULL;
            int c = 0;
#pragma unroll
            for (int i = 0; i < 8; i++) {
                unsigned long long q2 = 0ULL;
#pragma unroll
                for (int j = i; j < 8; j++) {
                    float cf = cfs[c * GG + cell];   // compile-time offsets
                    fma2(q2, pk1(cf), pv2[j]);
                    c++;
                }
                fma2(acc2, pv2[i], q2);
            }

            float acc0, acc1;
            unpk2(acc0, acc1, acc2);
            if (!active) { acc0 = 0.0f; acc1 = 0.0f; }   // pad threads contribute 0

            // Warp reduce both halves; no block barrier here.
#pragma unroll
            for (int o = 16; o > 0; o >>= 1) {
                acc0 += __shfl_xor_sync(0xffffffffu, acc0, o);
                acc1 += __shfl_xor_sync(0xffffffffu, acc1, o);
            }
            if (lane == 0) {
                red[buf][k2][0][warp] = acc0;
                red[buf][k2][1][warp] = acc1;
            }

            b = bn;
            npairs++;
        }

        __syncthreads();   // one barrier per batch (up to 8 b's)

        // Warp w finalizes b = bstart + w*stride  (w = 2*pair + half).
        if (warp < 2 * npairs) {
            float v = red[buf][warp >> 1][warp & 1][lane];
#pragma unroll
            for (int o = 16; o > 0; o >>= 1)
                v += __shfl_xor_sync(0xffffffffu, v, o);
            const int bo = bstart + warp * stride;
            if (lane == 0 && bo < nB) out[bo] = v;
        }

        buf ^= 1;
    }
}

extern "C" void kernel_launch(void* const* d_in, const int* in_sizes, int n_in,
                              void* d_out, int out_size)
{
    const float* param = (const float*)d_in[0];   // [B, 31, 31, 8] f32
    const float* coef  = (const float*)d_in[1];   // [31, 31, 36]   f32
    float* out = (float*)d_out;                    // [B] f32

    const int nB = in_sizes[0] / (GG * 8);
    const int smem = CC * GG * (int)sizeof(float);   // 138384 B

    static int configured = -1;
    if (configured < 0) {
        cudaFuncSetAttribute(sq2d_kernel,
                             cudaFuncAttributeMaxDynamicSharedMemorySize, smem);
        configured = 1;
    }

    int dev = 0, sms = 0;
    cudaGetDevice(&dev);
    cudaDeviceGetAttribute(&sms, cudaDevAttrMultiProcessorCount, dev);
    if (sms <= 0) sms = 148;
    if (sms > nB) sms = nB;

    sq2d_kernel<<<sms, NTHR, smem>>>(param, coef, out, nB, sms);
}